// round 12
// baseline (speedup 1.0000x reference)
#include <cuda_runtime.h>
#include <cuda_fp16.h>

#define N_NODES 100000
#define N_EDGES 3200000
#define IN_CH   128
#define HID     64
#define NEG_SLOPE 0.2f
#define CAP     96      // per-node bucket cap; deg ~ Poisson(32), P(deg>=96) ~ 1e-20
#define LOG2E   1.4426950408889634f

// ---------------- scratch (static device globals; no allocation) ----------------
__device__ __half2 g_hh[N_NODES * (HID / 2)];     // h in fp16, 12.8 MB (L2-resident)
__device__ float   g_asrc[N_NODES];               // a_src * log2(e)
__device__ float   g_adst[N_NODES];               // a_dst * log2(e)
__device__ float   g_selfex[N_NODES];
__device__ int     g_deg[N_NODES];
__device__ int4    g_bucket[(size_t)N_NODES * CAP];  // (src, edge_id, ex_bits, _)

// ---------------- helpers ----------------
__device__ __forceinline__ float leaky(float f) {
    return f > 0.f ? f : NEG_SLOPE * f;
}

// ---------------- K1: h = x @ W via HMMA  (+ exact a_src/a_dst) --------------
// Block: 128 nodes x 64 ch, K=128 in two 64-chunks staged as fp16 in SMEM.
// 8 warps, each owns 16 rows; 8 n-tiles of 8; mma.sync m16n8k16 f16->f32.
// a_src/a_dst computed EXACTLY in fp32 during the x load (dot with sWa),
// where sWa = W @ att is computed by each block from its staged W (cheap).
__global__ __launch_bounds__(256) void k_gemm(
    const float* __restrict__ x, const float* __restrict__ W,
    const float* __restrict__ att_s, const float* __restrict__ att_d)
{
    __shared__ __align__(16) __half xh[128][72];    // 64-k chunk
    __shared__ __align__(16) __half wsT[HID][136];  // W^T: [c][k], full K
    __shared__ float swas[IN_CH], swad[IN_CH];
    __shared__ float satt[2 * HID];

    const int tid  = threadIdx.x;
    const int lane = tid & 31;
    const int w    = tid >> 5;            // warp 0..7
    const int gid  = lane >> 2;           // group id 0..7
    const int q    = lane & 3;            // thread-in-group 0..3
    const int n0   = blockIdx.x * 128;

    if (tid < HID)            satt[tid] = att_s[tid];
    else if (tid < 2 * HID)   satt[tid] = att_d[tid - HID];

    // stage W^T as fp16 (once); also compute per-k Wa dots in fp32
    __syncthreads();
    #pragma unroll
    for (int i = 0; i < 8; i++) {
        int idx = tid + i * 256;          // 0..2047 float4 slots of W
        int k   = idx >> 4;               // 0..127
        int c4  = idx & 15;               // 0..15
        float4 wv = ((const float4*)W)[k * (HID / 4) + c4];
        wsT[c4 * 4 + 0][k] = __float2half_rn(wv.x);
        wsT[c4 * 4 + 1][k] = __float2half_rn(wv.y);
        wsT[c4 * 4 + 2][k] = __float2half_rn(wv.z);
        wsT[c4 * 4 + 3][k] = __float2half_rn(wv.w);
    }
    // Wa[k] = sum_c W[k][c]*att[c]; 256 threads -> 128 k x {src,dst}
    {
        int k   = tid >> 1;               // 0..127
        int sel = tid & 1;                // 0: src, 1: dst
        const float* row = W + k * HID;
        const float* av  = satt + sel * HID;
        float p = 0.f;
        #pragma unroll 8
        for (int c = 0; c < HID; c++) p = fmaf(row[c], av[c], p);
        if (sel == 0) swas[k] = p; else swad[k] = p;
    }

    const int row  = tid >> 1;            // loader row 0..127
    const int half = tid & 1;             // loader half of chunk
    const int node_l = n0 + row;

    float acc[8][4];
    #pragma unroll
    for (int t = 0; t < 8; t++)
        #pragma unroll
        for (int j = 0; j < 4; j++) acc[t][j] = 0.f;

    float ps = 0.f, pd = 0.f;

    for (int chunk = 0; chunk < 2; chunk++) {
        __syncthreads();

        #pragma unroll
        for (int i = 0; i < 8; i++) {
            int kk = chunk * 64 + half * 32 + i * 4;     // global k
            float4 v = make_float4(0.f, 0.f, 0.f, 0.f);
            if (node_l < N_NODES)
                v = ((const float4*)x)[node_l * (IN_CH / 4) + (kk >> 2)];
            int lk = half * 32 + i * 4;                  // local k in chunk
            *(half2*)&xh[row][lk + 0] = __floats2half2_rn(v.x, v.y);
            *(half2*)&xh[row][lk + 2] = __floats2half2_rn(v.z, v.w);
            ps = fmaf(v.x, swas[kk], fmaf(v.y, swas[kk + 1],
                 fmaf(v.z, swas[kk + 2], fmaf(v.w, swas[kk + 3], ps))));
            pd = fmaf(v.x, swad[kk], fmaf(v.y, swad[kk + 1],
                 fmaf(v.z, swad[kk + 2], fmaf(v.w, swad[kk + 3], pd))));
        }
        __syncthreads();

        #pragma unroll
        for (int ks = 0; ks < 4; ks++) {
            int lk = ks * 16;
            int gk = chunk * 64 + lk;
            int r  = w * 16 + gid;
            unsigned a0 = *(const unsigned*)&xh[r][lk + 2 * q];
            unsigned a1 = *(const unsigned*)&xh[r + 8][lk + 2 * q];
            unsigned a2 = *(const unsigned*)&xh[r][lk + 8 + 2 * q];
            unsigned a3 = *(const unsigned*)&xh[r + 8][lk + 8 + 2 * q];
            #pragma unroll
            for (int t = 0; t < 8; t++) {
                int n = t * 8 + gid;
                unsigned b0 = *(const unsigned*)&wsT[n][gk + 2 * q];
                unsigned b1 = *(const unsigned*)&wsT[n][gk + 8 + 2 * q];
                asm volatile(
                    "mma.sync.aligned.m16n8k16.row.col.f32.f16.f16.f32 "
                    "{%0,%1,%2,%3}, {%4,%5,%6,%7}, {%8,%9}, {%0,%1,%2,%3};"
                    : "+f"(acc[t][0]), "+f"(acc[t][1]),
                      "+f"(acc[t][2]), "+f"(acc[t][3])
                    : "r"(a0), "r"(a1), "r"(a2), "r"(a3), "r"(b0), "r"(b1));
            }
        }
    }

    // ---- attention epilogue: exact fp32 dots, stored pre-scaled by log2e ----
    ps += __shfl_xor_sync(0xFFFFFFFFu, ps, 1);
    pd += __shfl_xor_sync(0xFFFFFFFFu, pd, 1);
    if (half == 0 && node_l < N_NODES) {
        g_asrc[node_l]   = ps * LOG2E;
        g_adst[node_l]   = pd * LOG2E;
        g_selfex[node_l] = __expf(leaky(ps + pd));
        g_deg[node_l]    = 0;
    }

    // ---- h epilogue: D rows gid, gid+8 of this warp tile ----
    int nodeA = n0 + w * 16 + gid;
    int nodeB = nodeA + 8;
    #pragma unroll
    for (int t = 0; t < 8; t++) {
        if (nodeA < N_NODES)
            g_hh[nodeA * (HID / 2) + t * 4 + q] = __floats2half2_rn(acc[t][0], acc[t][1]);
        if (nodeB < N_NODES)
            g_hh[nodeB * (HID / 2) + t * 4 + q] = __floats2half2_rn(acc[t][2], acc[t][3]);
    }
}

// ---------------- K2: edge pass — exp + bucket fill -------------------------
// Latency/atomic-bound; the 2 gathers + EX2 hide under the atomic stalls.
// 16B bucket scatter touches the same ONE 32B sector per edge as 8B did.
__global__ __launch_bounds__(256) void k_edge(const int* __restrict__ ei,
                                              float* __restrict__ alpha)
{
    int e = blockIdx.x * blockDim.x + threadIdx.x;
    if (e >= N_EDGES) return;
    int s = ei[e];
    int d = ei[N_EDGES + e];
    if ((unsigned)s >= N_NODES) s = 0;   // degrade, don't crash
    if ((unsigned)d >= N_NODES) d = 0;

    float ex = exp2f(leaky(g_asrc[s] + g_adst[d]));   // single MUFU.EX2
    int pos = atomicAdd(&g_deg[d], 1);
    if (pos < CAP)
        g_bucket[(size_t)d * CAP + pos] = make_int4(s, e, __float_as_int(ex), 0);
    else
        alpha[e] = 0.f;   // overflow fallback (probability ~0 at CAP=96)
}

// ---------------- K3: per-node softmax sum + gather-aggregate + alpha --------
// One warp per node. Phase 1 is now PURE coalesced reads + adds (no gathers,
// no exp). Phase 2: 4 groups of 8 lanes; each group gathers a different edge's
// h row (lane = uint4 = 8 channels) so 4 L2 loads are in flight per trip.
__global__ __launch_bounds__(256) void k_agg(const float* __restrict__ bias,
                                             float* __restrict__ out,
                                             float* __restrict__ alpha)
{
    const int tid  = threadIdx.x;
    const int lane = tid & 31;
    const int node = blockIdx.x * 8 + (tid >> 5);
    if (node >= N_NODES) return;

    const int cnt = min(g_deg[node], CAP);
    const int4* bk = &g_bucket[(size_t)node * CAP];
    const float selfex = g_selfex[node];

    // ---- phase 1: coalesced bucket read + warp sum + alpha scatter ----
    int   srcv[3];
    int   eidv[3];
    float exv[3];
    float mysum = 0.f;
    #pragma unroll
    for (int c = 0; c < 3; c++) {
        int idx = c * 32 + lane;
        int4 p = (idx < cnt) ? bk[idx] : make_int4(0, -1, 0, 0);
        srcv[c] = p.x;
        eidv[c] = p.y;
        exv[c]  = __int_as_float(p.z);
        mysum += exv[c];
    }
    #pragma unroll
    for (int o = 16; o; o >>= 1)
        mysum += __shfl_xor_sync(0xFFFFFFFFu, mysum, o);
    float inv = 1.f / (mysum + selfex);

    #pragma unroll
    for (int c = 0; c < 3; c++)
        if (eidv[c] >= 0) alpha[eidv[c]] = exv[c] * inv;
    if (lane == 0) alpha[N_EDGES + node] = selfex * inv;

    // ---- phase 2: grouped gather-aggregate ----
    const int g   = lane >> 3;    // edge group 0..3
    const int sub = lane & 7;     // 8 channels (16B) per lane
    float acc[8] = {0.f, 0.f, 0.f, 0.f, 0.f, 0.f, 0.f, 0.f};

    // self loop (group 0 only)
    if (g == 0) {
        uint4 hv = *(const uint4*)&g_hh[(size_t)node * (HID / 2) + sub * 4];
        const __half2* hp = (const __half2*)&hv;
        #pragma unroll
        for (int q = 0; q < 4; q++) {
            float2 f = __half22float2(hp[q]);
            acc[q * 2 + 0] = fmaf(selfex, f.x, acc[q * 2 + 0]);
            acc[q * 2 + 1] = fmaf(selfex, f.y, acc[q * 2 + 1]);
        }
    }

    #pragma unroll
    for (int c = 0; c < 3; c++) {
        int rem = cnt - c * 32;
        if (rem <= 0) break;
        if (rem > 32) rem = 32;
        for (int jb = 0; jb < rem; jb += 4) {
            int   s  = __shfl_sync(0xFFFFFFFFu, srcv[c], jb + g);
            float ex = __shfl_sync(0xFFFFFFFFu, exv[c],  jb + g);
            if (jb + g < rem) {
                uint4 hv = *(const uint4*)&g_hh[(size_t)s * (HID / 2) + sub * 4];
                const __half2* hp = (const __half2*)&hv;
                #pragma unroll
                for (int q = 0; q < 4; q++) {
                    float2 f = __half22float2(hp[q]);
                    acc[q * 2 + 0] = fmaf(ex, f.x, acc[q * 2 + 0]);
                    acc[q * 2 + 1] = fmaf(ex, f.y, acc[q * 2 + 1]);
                }
            }
        }
    }

    // fold the 4 groups (lanes sub, sub+8, sub+16, sub+24 hold same channels)
    #pragma unroll
    for (int q = 0; q < 8; q++) {
        acc[q] += __shfl_xor_sync(0xFFFFFFFFu, acc[q], 8);
        acc[q] += __shfl_xor_sync(0xFFFFFFFFu, acc[q], 16);
    }

    if (g == 0) {   // lanes 0..7 write channels sub*8 .. sub*8+7
        float4 b0 = ((const float4*)bias)[sub * 2 + 0];
        float4 b1 = ((const float4*)bias)[sub * 2 + 1];
        float4 o0 = make_float4(acc[0] * inv + b0.x, acc[1] * inv + b0.y,
                                acc[2] * inv + b0.z, acc[3] * inv + b0.w);
        float4 o1 = make_float4(acc[4] * inv + b1.x, acc[5] * inv + b1.y,
                                acc[6] * inv + b1.z, acc[7] * inv + b1.w);
        float4* op = (float4*)&out[(size_t)node * HID + sub * 8];
        op[0] = o0;
        op[1] = o1;
    }
}

// ---------------- launch ----------------
extern "C" void kernel_launch(void* const* d_in, const int* in_sizes, int n_in,
                              void* d_out, int out_size)
{
    const float* x     = (const float*)d_in[0];
    const int*   ei    = (const int*)d_in[1];     // int32 (JAX x64 disabled)
    const float* W     = (const float*)d_in[2];
    const float* att_s = (const float*)d_in[3];
    const float* att_d = (const float*)d_in[4];
    const float* bias  = (const float*)d_in[5];

    float* out   = (float*)d_out;
    float* alpha = out + (size_t)N_NODES * HID;   // output layout: [out | alpha]

    k_gemm<<<(N_NODES + 127) / 128, 256>>>(x, W, att_s, att_d);
    k_edge<<<(N_EDGES + 255) / 256, 256>>>(ei, alpha);
    k_agg <<<(N_NODES + 7) / 8, 256>>>(bias, out, alpha);
}

// round 13
// speedup vs baseline: 1.3107x; 1.3107x over previous
#include <cuda_runtime.h>
#include <cuda_fp16.h>

#define N_NODES 100000
#define N_EDGES 3200000
#define IN_CH   128
#define HID     64
#define NEG_SLOPE 0.2f
#define CAP     96      // per-node bucket cap; deg ~ Poisson(32), P(deg>=96) ~ 1e-20

// ---------------- scratch (static device globals; no allocation) ----------------
__device__ __half2 g_hh[N_NODES * (HID / 2)];     // h in fp16, 12.8 MB (L2-resident)
__device__ float   g_asrc[N_NODES];
__device__ float   g_adst[N_NODES];
__device__ float   g_selfex[N_NODES];
__device__ int     g_deg[N_NODES];
__device__ int2    g_bucket[(size_t)N_NODES * CAP];  // (src, edge_id), 76.8 MB

// ---------------- helpers ----------------
__device__ __forceinline__ float leaky(float f) {
    return f > 0.f ? f : NEG_SLOPE * f;
}
__device__ __forceinline__ unsigned long long splat2(float v) {
    unsigned long long r;
    asm("mov.b64 %0, {%1, %1};" : "=l"(r) : "f"(v));
    return r;
}
__device__ __forceinline__ void fma2(unsigned long long& acc,
                                     unsigned long long a, unsigned long long b) {
#if defined(__CUDA_ARCH__) && (__CUDA_ARCH__ >= 1000)
    asm("fma.rn.f32x2 %0, %1, %2, %0;" : "+l"(acc) : "l"(a), "l"(b));
#else
    float2* pa = (float2*)&a; float2* pb = (float2*)&b; float2* pc = (float2*)&acc;
    pc->x = fmaf(pa->x, pb->x, pc->x); pc->y = fmaf(pa->y, pb->y, pc->y);
#endif
}
__device__ __forceinline__ float2 unpack2(unsigned long long v) {
    float lo, hi;
    asm("mov.b64 {%0, %1}, %2;" : "=f"(lo), "=f"(hi) : "l"(v));
    return make_float2(lo, hi);
}

// ---------------- K0: zero g_deg (edge's only dependency) --------------------
__global__ __launch_bounds__(256) void k_init()
{
    int i = blockIdx.x * blockDim.x + threadIdx.x;
    if (i < N_NODES) g_deg[i] = 0;
}

// ---------------- K1: h = x @ W  (+ a_src, a_dst, selfex) --------------------
// R6 kernel (measured 44.5us). 128 nodes x 64 ch per block, K in chunks of 32.
// xs TRANSPOSED [k][node] -> LDS.64 gives natural node-pair f32x2 A operands.
// Fires the PDL trigger at block start so k_edge can overlap.
#define KC 32
#define XPAD 130   // row stride (words): even -> 8B-aligned node pairs

__global__ __launch_bounds__(256) void k_gemm(
    const float* __restrict__ x, const float* __restrict__ W,
    const float* __restrict__ att_s, const float* __restrict__ att_d)
{
#if defined(__CUDA_ARCH__) && (__CUDA_ARCH__ >= 900)
    asm volatile("griddepcontrol.launch_dependents;" ::: "memory");
#endif

    __shared__ __align__(16) float xs[KC][XPAD];  // [k][node(128)]
    __shared__ __align__(16) float ws[KC][64];    // [k][c]

    const int tid = threadIdx.x;
    const int tx = tid & 15;       // channel quad (16 -> 64 ch)
    const int ty = tid >> 4;       // node octet (16 -> 128 nodes)
    const int n0 = blockIdx.x * 128;

    unsigned long long acc[4][4];  // [node pair][channel], pair = {n, n+1}
    #pragma unroll
    for (int p = 0; p < 4; p++)
        #pragma unroll
        for (int c = 0; c < 4; c++) acc[p][c] = 0ull;

    for (int kt = 0; kt < IN_CH / KC; kt++) {
        // load x chunk transposed: 32 k x 128 nodes
        #pragma unroll
        for (int i = 0; i < 4; i++) {
            int li = tid + i * 256;        // 0..1023 float4 slots
            int n  = li >> 3;              // node 0..127
            int k4 = li & 7;               // k quad 0..7 (32 k)
            int node = n0 + n;
            float4 v = make_float4(0.f, 0.f, 0.f, 0.f);
            if (node < N_NODES)
                v = ((const float4*)x)[node * (IN_CH / 4) + kt * 8 + k4];
            xs[k4 * 4 + 0][n] = v.x;
            xs[k4 * 4 + 1][n] = v.y;
            xs[k4 * 4 + 2][n] = v.z;
            xs[k4 * 4 + 3][n] = v.w;
        }
        // load W chunk: 32 k x 64 c
        #pragma unroll
        for (int i = 0; i < 2; i++) {
            int li = tid + i * 256;        // 0..511 float4 slots
            int k  = li >> 4;
            int c4 = li & 15;
            ((float4*)ws[k])[c4] = ((const float4*)W)[(kt * KC + k) * (HID / 4) + c4];
        }
        __syncthreads();

        #pragma unroll
        for (int k = 0; k < KC; k++) {
            float4 bv = *(const float4*)&ws[k][tx * 4];
            unsigned long long b0 = splat2(bv.x);
            unsigned long long b1 = splat2(bv.y);
            unsigned long long b2 = splat2(bv.z);
            unsigned long long b3 = splat2(bv.w);
            const float* xrow = &xs[k][ty * 8];
            #pragma unroll
            for (int p = 0; p < 4; p++) {
                unsigned long long a = *(const unsigned long long*)(xrow + 2 * p);
                fma2(acc[p][0], a, b0);
                fma2(acc[p][1], a, b1);
                fma2(acc[p][2], a, b2);
                fma2(acc[p][3], a, b3);
            }
        }
        __syncthreads();
    }

    // epilogue: 8 nodes per thread (4 pairs), channels tx*4..tx*4+3
    float4 as4 = ((const float4*)att_s)[tx];
    float4 ad4 = ((const float4*)att_d)[tx];
    #pragma unroll
    for (int p = 0; p < 4; p++) {
        float2 c0 = unpack2(acc[p][0]);   // (node even, node odd) channel 0
        float2 c1 = unpack2(acc[p][1]);
        float2 c2 = unpack2(acc[p][2]);
        float2 c3 = unpack2(acc[p][3]);
        #pragma unroll
        for (int half = 0; half < 2; half++) {
            int node = n0 + ty * 8 + 2 * p + half;
            float f0 = half ? c0.y : c0.x;
            float f1 = half ? c1.y : c1.x;
            float f2 = half ? c2.y : c2.x;
            float f3 = half ? c3.y : c3.x;
            float ps = f0 * as4.x + f1 * as4.y + f2 * as4.z + f3 * as4.w;
            float pd = f0 * ad4.x + f1 * ad4.y + f2 * ad4.z + f3 * ad4.w;
            #pragma unroll
            for (int o = 8; o; o >>= 1) {
                ps += __shfl_xor_sync(0xFFFFFFFFu, ps, o);
                pd += __shfl_xor_sync(0xFFFFFFFFu, pd, o);
            }
            if (node < N_NODES) {
                g_hh[node * (HID / 2) + tx * 2 + 0] = __floats2half2_rn(f0, f1);
                g_hh[node * (HID / 2) + tx * 2 + 1] = __floats2half2_rn(f2, f3);
                if (tx == 0) {
                    g_asrc[node]   = ps;
                    g_adst[node]   = pd;
                    g_selfex[node] = __expf(leaky(ps + pd));
                    // NOTE: g_deg zeroed in k_init (k_edge may overlap this kernel)
                }
            }
        }
    }
}

// ---------------- K2: edge pass — bucket fill only (1 atomic/edge) -----------
// Launched with programmatic stream serialization: overlaps k_gemm (reads only
// ei and g_deg, which k_init finished before k_gemm started).
__global__ __launch_bounds__(256) void k_edge(const int* __restrict__ ei,
                                              float* __restrict__ alpha)
{
    int e = blockIdx.x * blockDim.x + threadIdx.x;
    if (e >= N_EDGES) return;
    int s = ei[e];
    int d = ei[N_EDGES + e];
    if ((unsigned)s >= N_NODES) s = 0;   // degrade, don't crash
    if ((unsigned)d >= N_NODES) d = 0;

    int pos = atomicAdd(&g_deg[d], 1);
    if (pos < CAP)
        g_bucket[(size_t)d * CAP + pos] = make_int2(s, e);
    else
        alpha[e] = 0.f;   // overflow fallback (probability ~0 at CAP=96)
}

// ---------------- K3: per-node softmax + gather-aggregate + alpha ------------
// One warp per node (R6 kernel). Phase 1: lanes read bucket entries, compute
// exp, warp-reduce sum, scatter normalized alpha. Phase 2: 4 groups of 8
// lanes gather different edges' h rows (lane = uint4 = 8 channels), fold.
__global__ __launch_bounds__(256) void k_agg(const float* __restrict__ bias,
                                             float* __restrict__ out,
                                             float* __restrict__ alpha)
{
    const int tid  = threadIdx.x;
    const int lane = tid & 31;
    const int node = blockIdx.x * 8 + (tid >> 5);
    if (node >= N_NODES) return;

    const int cnt = min(g_deg[node], CAP);
    const int2* bk = &g_bucket[(size_t)node * CAP];
    const float adst   = g_adst[node];
    const float selfex = g_selfex[node];

    // ---- phase 1: per-lane exp + warp sum + alpha scatter ----
    int   srcv[3];
    int   eidv[3];
    float exv[3];
    float mysum = 0.f;
    #pragma unroll
    for (int c = 0; c < 3; c++) {
        int idx = c * 32 + lane;
        int2 p = (idx < cnt) ? bk[idx] : make_int2(0, -1);
        srcv[c] = p.x;
        eidv[c] = p.y;
        float ex = (idx < cnt) ? __expf(leaky(g_asrc[p.x] + adst)) : 0.f;
        exv[c] = ex;
        mysum += ex;
    }
    #pragma unroll
    for (int o = 16; o; o >>= 1)
        mysum += __shfl_xor_sync(0xFFFFFFFFu, mysum, o);
    float inv = 1.f / (mysum + selfex);

    #pragma unroll
    for (int c = 0; c < 3; c++)
        if (eidv[c] >= 0) alpha[eidv[c]] = exv[c] * inv;
    if (lane == 0) alpha[N_EDGES + node] = selfex * inv;

    // ---- phase 2: grouped gather-aggregate ----
    const int g   = lane >> 3;    // edge group 0..3
    const int sub = lane & 7;     // 8 channels (16B) per lane
    float acc[8] = {0.f, 0.f, 0.f, 0.f, 0.f, 0.f, 0.f, 0.f};

    // self loop (group 0 only)
    if (g == 0) {
        uint4 hv = *(const uint4*)&g_hh[(size_t)node * (HID / 2) + sub * 4];
        const __half2* hp = (const __half2*)&hv;
        #pragma unroll
        for (int q = 0; q < 4; q++) {
            float2 f = __half22float2(hp[q]);
            acc[q * 2 + 0] = fmaf(selfex, f.x, acc[q * 2 + 0]);
            acc[q * 2 + 1] = fmaf(selfex, f.y, acc[q * 2 + 1]);
        }
    }

    #pragma unroll
    for (int c = 0; c < 3; c++) {
        int rem = cnt - c * 32;
        if (rem <= 0) break;
        if (rem > 32) rem = 32;
        for (int jb = 0; jb < rem; jb += 4) {
            int   s  = __shfl_sync(0xFFFFFFFFu, srcv[c], jb + g);
            float ex = __shfl_sync(0xFFFFFFFFu, exv[c],  jb + g);
            if (jb + g < rem) {
                uint4 hv = *(const uint4*)&g_hh[(size_t)s * (HID / 2) + sub * 4];
                const __half2* hp = (const __half2*)&hv;
                #pragma unroll
                for (int q = 0; q < 4; q++) {
                    float2 f = __half22float2(hp[q]);
                    acc[q * 2 + 0] = fmaf(ex, f.x, acc[q * 2 + 0]);
                    acc[q * 2 + 1] = fmaf(ex, f.y, acc[q * 2 + 1]);
                }
            }
        }
    }

    // fold the 4 groups (lanes sub, sub+8, sub+16, sub+24 hold same channels)
    #pragma unroll
    for (int q = 0; q < 8; q++) {
        acc[q] += __shfl_xor_sync(0xFFFFFFFFu, acc[q], 8);
        acc[q] += __shfl_xor_sync(0xFFFFFFFFu, acc[q], 16);
    }

    if (g == 0) {   // lanes 0..7 write channels sub*8 .. sub*8+7
        float4 b0 = ((const float4*)bias)[sub * 2 + 0];
        float4 b1 = ((const float4*)bias)[sub * 2 + 1];
        float4 o0 = make_float4(acc[0] * inv + b0.x, acc[1] * inv + b0.y,
                                acc[2] * inv + b0.z, acc[3] * inv + b0.w);
        float4 o1 = make_float4(acc[4] * inv + b1.x, acc[5] * inv + b1.y,
                                acc[6] * inv + b1.z, acc[7] * inv + b1.w);
        float4* op = (float4*)&out[(size_t)node * HID + sub * 8];
        op[0] = o0;
        op[1] = o1;
    }
}

// ---------------- launch ----------------
extern "C" void kernel_launch(void* const* d_in, const int* in_sizes, int n_in,
                              void* d_out, int out_size)
{
    const float* x     = (const float*)d_in[0];
    const int*   ei    = (const int*)d_in[1];     // int32 (JAX x64 disabled)
    const float* W     = (const float*)d_in[2];
    const float* att_s = (const float*)d_in[3];
    const float* att_d = (const float*)d_in[4];
    const float* bias  = (const float*)d_in[5];

    float* out   = (float*)d_out;
    float* alpha = out + (size_t)N_NODES * HID;   // output layout: [out | alpha]

    // init -> gemm (fires PDL trigger at start) -> edge (overlaps gemm) -> agg
    k_init<<<(N_NODES + 255) / 256, 256>>>();
    k_gemm<<<(N_NODES + 127) / 128, 256>>>(x, W, att_s, att_d);

    {
        cudaLaunchConfig_t cfg = {};
        cfg.gridDim  = dim3((N_EDGES + 255) / 256, 1, 1);
        cfg.blockDim = dim3(256, 1, 1);
        cudaLaunchAttribute attrs[1];
        attrs[0].id = cudaLaunchAttributeProgrammaticStreamSerialization;
        attrs[0].val.programmaticStreamSerializationAllowed = 1;
        cfg.attrs = attrs;
        cfg.numAttrs = 1;
        cudaLaunchKernelEx(&cfg, k_edge, ei, alpha);
    }

    k_agg<<<(N_NODES + 7) / 8, 256>>>(bias, out, alpha);
}